// round 16
// baseline (speedup 1.0000x reference)
#include <cuda_runtime.h>

#define BB 16
#define NN 2048
#define KK 16
#define CC 64
#define BN (BB * NN)

#define THR 256     // knn threads per block (8 warps = 2 slabs x 4 warps)
#define KBUF 16     // per-thread idx buffer entries
#define CHK 128     // far-loop chunk size
#define NEARW 120   // near candidates per side

#define NBKT 256
#define QLO  (-6.0f)
#define QS   (256.0f / 12.0f)

// ---------------- scratch ---------------------------------------------------
__device__ float  g_A  [BN * CC];
__device__ float  g_BV [BN * 2*CC];
__device__ int    g_nbr[BN * KK];
__device__ float4 g_sorted[BN];
__device__ int    g_cum[BB * (NBKT + 1)];
__device__ uint2  g_p1 [BN * KK];   // exact near-240 top-16 per target (d2, rank)
__device__ float  g_Wda[CC * CC];
__device__ float  g_Wsa[CC * CC];
__device__ float  g_Wpa[3 * CC];
__device__ float  g_biasL[CC];

__device__ __forceinline__ int qbucket(float x) {
    int b = (int)floorf((x - QLO) * QS);
    if (b < 0) b = 0;
    if (b > NBKT - 1) b = NBKT - 1;
    return b;
}

// ---------------- k0: combine weights ---------------------------------------
__global__ void combine_kernel(const float* __restrict__ W_pos,
                               const float* __restrict__ b_pos,
                               const float* __restrict__ W_attn,
                               const float* __restrict__ b_attn,
                               const float* __restrict__ W_src,
                               const float* __restrict__ W_dst) {
    int tid = threadIdx.x;
    int blk = blockIdx.x;
    if (blk < 16) {
        int r = tid >> 6, c = tid & 63;
        int k = blk * 4 + r;
        float a1 = 0.f, a2 = 0.f;
#pragma unroll 8
        for (int m = 0; m < 64; m++) {
            float w = W_attn[m * 64 + c];
            a1 = fmaf(W_dst[k * 64 + m], w, a1);
            a2 = fmaf(W_src[k * 64 + m], w, a2);
        }
        g_Wda[k * 64 + c] = a1;
        g_Wsa[k * 64 + c] = a2;
    } else {
        if (tid < 192) {
            int d = tid >> 6, c = tid & 63;
            float a = 0.f;
#pragma unroll 8
            for (int m = 0; m < 64; m++)
                a = fmaf(W_pos[d * 64 + m], W_attn[m * 64 + c], a);
            g_Wpa[tid] = a;
        } else {
            int c = tid - 192;
            float a = b_attn[c];
#pragma unroll 8
            for (int m = 0; m < 64; m++)
                a = fmaf(b_pos[m], W_attn[m * 64 + c], a);
            g_biasL[c] = a;
        }
    }
}

// ---------------- k1: per-point GEMMs ---------------------------------------
__global__ void feat_gemm_kernel(const float* __restrict__ x,
                                 const float* __restrict__ W_val) {
    __shared__ float xs[64][68];
    __shared__ float ws[64 * 64];
    int tid = threadIdx.x;
    int p0 = blockIdx.x * 64;
    int m = blockIdx.y;
    const float* src = (m == 0) ? g_Wda : (m == 1) ? g_Wsa : W_val;

    for (int idx = tid; idx < 4096; idx += 256) {
        int p = idx >> 6, k = idx & 63;
        xs[k][p] = x[(p0 + p) * 64 + k];
        ws[idx] = src[idx];
    }
    __syncthreads();

    int tx = tid & 15, ty = tid >> 4;
    float acc[4][4];
#pragma unroll
    for (int i = 0; i < 4; i++)
#pragma unroll
        for (int j = 0; j < 4; j++) acc[i][j] = 0.f;

#pragma unroll 8
    for (int k = 0; k < 64; k++) {
        float4 xv = *(const float4*)&xs[k][ty * 4];
        float4 wv = *(const float4*)&ws[k * 64 + tx * 4];
        acc[0][0] = fmaf(xv.x, wv.x, acc[0][0]);
        acc[0][1] = fmaf(xv.x, wv.y, acc[0][1]);
        acc[0][2] = fmaf(xv.x, wv.z, acc[0][2]);
        acc[0][3] = fmaf(xv.x, wv.w, acc[0][3]);
        acc[1][0] = fmaf(xv.y, wv.x, acc[1][0]);
        acc[1][1] = fmaf(xv.y, wv.y, acc[1][1]);
        acc[1][2] = fmaf(xv.y, wv.z, acc[1][2]);
        acc[1][3] = fmaf(xv.y, wv.w, acc[1][3]);
        acc[2][0] = fmaf(xv.z, wv.x, acc[2][0]);
        acc[2][1] = fmaf(xv.z, wv.y, acc[2][1]);
        acc[2][2] = fmaf(xv.z, wv.z, acc[2][2]);
        acc[2][3] = fmaf(xv.z, wv.w, acc[2][3]);
        acc[3][0] = fmaf(xv.w, wv.x, acc[3][0]);
        acc[3][1] = fmaf(xv.w, wv.y, acc[3][1]);
        acc[3][2] = fmaf(xv.w, wv.z, acc[3][2]);
        acc[3][3] = fmaf(xv.w, wv.w, acc[3][3]);
    }

    int c0 = tx * 4;
#pragma unroll
    for (int i = 0; i < 4; i++) {
        int p = p0 + ty * 4 + i;
        if (m == 0) {
            *(float4*)&g_A[(size_t)p * 64 + c0] =
                make_float4(acc[i][0], acc[i][1], acc[i][2], acc[i][3]);
        } else if (m == 1) {
            *(float2*)&g_BV[(size_t)p * 128 + c0 * 2]     = make_float2(acc[i][0], acc[i][1]);
            *(float2*)&g_BV[(size_t)p * 128 + c0 * 2 + 4] = make_float2(acc[i][2], acc[i][3]);
        } else {
            *(float2*)&g_BV[(size_t)p * 128 + c0 * 2 + 2] = make_float2(acc[i][0], acc[i][1]);
            *(float2*)&g_BV[(size_t)p * 128 + c0 * 2 + 6] = make_float2(acc[i][2], acc[i][3]);
        }
    }
}

// ---------------- k2a: per-cloud bucket (counting) sort by quantized x -------
__global__ void __launch_bounds__(1024) sort_kernel(const float* __restrict__ pos) {
    __shared__ int hist[NBKT];
    __shared__ int cum[NBKT + 1];
    __shared__ int cursor[NBKT];
    __shared__ int wsum[8];

    int tid = threadIdx.x;
    int lane = tid & 31;
    int w = tid >> 5;
    int base = blockIdx.x * NN;

    if (tid < NBKT) hist[tid] = 0;
    __syncthreads();

    float4 v[2];
    int b[2];
#pragma unroll
    for (int k = 0; k < 2; k++) {
        int i = tid + k * 1024;
        const float* p = pos + (size_t)(base + i) * 3;
        float px = p[0];
        v[k] = make_float4(px, p[1], p[2], __int_as_float(base + i));
        b[k] = qbucket(px);
        atomicAdd(&hist[b[k]], 1);
    }
    __syncthreads();

    if (tid < NBKT) {
        int val = hist[tid];
#pragma unroll
        for (int o = 1; o < 32; o <<= 1) {
            int n = __shfl_up_sync(0xffffffffu, val, o);
            if (lane >= o) val += n;
        }
        if (lane == 31) wsum[w] = val;
        __syncthreads();
        if (tid == 0) {
            int a = 0;
#pragma unroll
            for (int i = 0; i < 8; i++) { int t = wsum[i]; wsum[i] = a; a += t; }
        }
        __syncthreads();
        int incl = val + wsum[w];
        cum[tid + 1] = incl;
        if (tid == 0) cum[0] = 0;
    } else {
        __syncthreads();
        __syncthreads();
    }
    __syncthreads();

    if (tid < NBKT) cursor[tid] = cum[tid];
    if (tid <= NBKT) g_cum[blockIdx.x * (NBKT + 1) + tid] = cum[tid];
    __syncthreads();

#pragma unroll
    for (int k = 0; k < 2; k++) {
        int off = atomicAdd(&cursor[b[k]], 1);
        g_sorted[base + off] = v[k];
    }
}

// ---------------- knn helpers ------------------------------------------------
__device__ __forceinline__ void insert16(float (&bd)[KK], int (&bi)[KK],
                                         float d, int id) {
#pragma unroll
    for (int s = 0; s < KK; s++) {
        bool p = d < bd[s];
        float nbd = p ? d : bd[s];
        float nd  = p ? bd[s] : d;
        int   nbi = p ? id : bi[s];
        int   nid = p ? bi[s] : id;
        bd[s] = nbd; d = nd; bi[s] = nbi; id = nid;
    }
}

// broadcast scan over parity candidates in [jb, je); buffered, drain at end
__device__ __forceinline__ void scan_par(const float4* __restrict__ sp,
                                         int* __restrict__ buf, int tid,
                                         int jb, int je, int par, int s,
                                         float4 pi,
                                         float (&bd)[KK], int (&bi)[KK]) {
    int j0 = jb + (((jb & 1) != par) ? 1 : 0);
    int cnt = 0;
#pragma unroll 4
    for (int j = j0; j < je; j += 2) {
        float4 p = sp[j];
        float dx = pi.x - p.x, dy = pi.y - p.y, dz = pi.z - p.z;
        float d2 = fmaf(dx, dx, fmaf(dy, dy, dz * dz));
        if (d2 < bd[KK - 1] && j != s) {
            if (cnt < KBUF) { buf[cnt * THR + tid] = j; cnt++; }
            else insert16(bd, bi, d2, j);
        }
    }
    unsigned wmax = __reduce_max_sync(0xffffffffu, (unsigned)cnt);
    for (unsigned m = 0; m < wmax; m++) {
        if ((int)m < cnt) {
            int j = buf[m * THR + tid];
            float4 p = sp[j];
            float dx = pi.x - p.x, dy = pi.y - p.y, dz = pi.z - p.z;
            float d2 = fmaf(dx, dx, fmaf(dy, dy, dz * dz));
            if (d2 < bd[KK - 1]) insert16(bd, bi, d2, j);
        }
    }
}

// bitonic merge of two sorted-asc disjoint 16-lists -> smallest 16, sorted asc
__device__ __forceinline__ void merge16(float (&bd)[KK], int (&bi)[KK],
                                        const float (&ed)[KK], const int (&ei)[KK]) {
    float nd[KK];
    int ni[KK];
#pragma unroll
    for (int i = 0; i < KK; i++) {
        float od = ed[KK - 1 - i];
        int   oi = ei[KK - 1 - i];
        bool take = od < bd[i];
        nd[i] = take ? od : bd[i];
        ni[i] = take ? oi : bi[i];
    }
#pragma unroll
    for (int d = 8; d >= 1; d >>= 1)
#pragma unroll
        for (int i = 0; i < KK; i++) {
            int l = i | d;
            if (l != i) {
                bool sw = nd[i] > nd[l];
                float tv = sw ? nd[l] : nd[i];
                float tw = sw ? nd[i] : nd[l];
                int   ui = sw ? ni[l] : ni[i];
                int   uj = sw ? ni[i] : ni[l];
                nd[i] = tv; nd[l] = tw; ni[i] = ui; ni[l] = uj;
            }
        }
#pragma unroll
    for (int i = 0; i < KK; i++) { bd[i] = nd[i]; bi[i] = ni[i]; }
}

// ---------------- k2b: P1 — exact near-240 top-16, 4 warps/slab --------------
__global__ void __launch_bounds__(THR) knn_p1_kernel() {
    extern __shared__ char ksm[];
    float4* sp    = (float4*)ksm;                             // 32 KB
    int*    buf   = (int*)(ksm + 32768);                      // 16 KB
    uint2*  lists = (uint2*)(ksm + 32768 + 16384);            // 24 KB

    int tid  = threadIdx.x;
    int lane = tid & 31;
    int warp = tid >> 5;
    int slabq = warp >> 2;    // 0..1
    int q     = warp & 3;
    int side  = q & 1;
    int par   = q >> 1;

    int base = blockIdx.y * NN;
    for (int i = tid; i < NN; i += THR)
        sp[i] = g_sorted[base + i];
    __syncthreads();

    int slab = blockIdx.x + 32 * slabq;  // 0..63
    int ws = slab * 32;
    int mid = ws + 16;                   // mid is even
    int s = ws + lane;
    float4 pi = sp[s];

    int lo0 = mid - NEARW; if (lo0 < 0) lo0 = 0;
    int hi0 = mid + NEARW; if (hi0 > NN) hi0 = NN;

    // j0 = closest own-side own-parity rank
    int j0 = side ? (mid + par) : (mid - 2 + par);

    float bd[KK];
    int bi[KK];
#pragma unroll
    for (int t = 0; t < KK; t++) {
        int j = side ? (j0 + 2 * t) : (j0 - 2 * t);
        bool valid = side ? (j < hi0) : (j >= lo0);
        int jc = j < 0 ? 0 : (j > NN - 1 ? NN - 1 : j);
        float4 p = sp[jc];
        float dx = pi.x - p.x, dy = pi.y - p.y, dz = pi.z - p.z;
        float d2 = fmaf(dx, dx, fmaf(dy, dy, dz * dz));
        bd[t] = (valid && j != s) ? d2 : 3.4e38f;
        bi[t] = jc;
    }
    // bitonic sort 16 ascending
#pragma unroll
    for (int k = 2; k <= 16; k <<= 1)
#pragma unroll
        for (int jj = k >> 1; jj > 0; jj >>= 1)
#pragma unroll
            for (int i = 0; i < 16; i++) {
                int l = i ^ jj;
                if (l > i) {
                    bool up = ((i & k) == 0);
                    bool sw = up ? (bd[i] > bd[l]) : (bd[i] < bd[l]);
                    float tv = sw ? bd[l] : bd[i];
                    float tw = sw ? bd[i] : bd[l];
                    int   ui = sw ? bi[l] : bi[i];
                    int   uj = sw ? bi[i] : bi[l];
                    bd[i] = tv; bd[l] = tw; bi[i] = ui; bi[l] = uj;
                }
            }

    if (side == 0) {
        // remaining left-parity candidates: j <= j0-32, j >= lo0
        int je = j0 - 30;                 // exclusive; largest scanned = j0-32
        int c1 = je - 64; if (c1 < lo0) c1 = lo0;
        if (c1 < je)  scan_par(sp, buf, tid, c1, je, par, s, pi, bd, bi);
        if (lo0 < c1) scan_par(sp, buf, tid, lo0, c1, par, s, pi, bd, bi);
    } else {
        // remaining right-parity candidates: j >= j0+32, j < hi0
        int jb = j0 + 32;
        int c1 = jb + 64; if (c1 > hi0) c1 = hi0;
        if (jb < c1)  scan_par(sp, buf, tid, jb, c1, par, s, pi, bd, bi);
        if (c1 < hi0) scan_par(sp, buf, tid, c1, hi0, par, s, pi, bd, bi);
    }

    if (q != 0) {
#pragma unroll
        for (int k = 0; k < KK; k++)
            lists[slabq * (3 * 32 * KK) + (q - 1) * (32 * KK) + k * 32 + lane] =
                make_uint2(__float_as_uint(bd[k]), (unsigned)bi[k]);
    }
    __syncthreads();

    if (q == 0) {
        // merge 3 disjoint sibling lists (bitonic pair-merges)
#pragma unroll
        for (int l = 0; l < 3; l++) {
            float ed[KK];
            int ei[KK];
#pragma unroll
            for (int k = 0; k < KK; k++) {
                uint2 e = lists[slabq * (3 * 32 * KK) + l * (32 * KK) + k * 32 + lane];
                ed[k] = __uint_as_float(e.x);
                ei[k] = (int)e.y;
            }
            merge16(bd, bi, ed, ei);
        }
        uint4* dst = (uint4*)&g_p1[((size_t)base + s) * KK];
#pragma unroll
        for (int t = 0; t < 8; t++)
            dst[t] = make_uint4(__float_as_uint(bd[2 * t]), (unsigned)bi[2 * t],
                                __float_as_uint(bd[2 * t + 1]), (unsigned)bi[2 * t + 1]);
    }
}

// ---------------- k2c: P2 — far window scan, 4 warps/slab, seeded tight ------
__global__ void __launch_bounds__(THR) knn_p2_kernel() {
    extern __shared__ char ksm[];
    float4* sp    = (float4*)ksm;                             // 32 KB
    int*    buf   = (int*)(ksm + 32768);                      // 16 KB
    uint2*  lists = (uint2*)(ksm + 32768 + 16384);            // 24 KB
    int*    scum  = (int*)(ksm + 32768 + 16384 + 24576);      // 1040 B

    int tid  = threadIdx.x;
    int lane = tid & 31;
    int warp = tid >> 5;
    int slabq = warp >> 2;
    int q     = warp & 3;
    int side  = q & 1;
    int par   = q >> 1;

    int base = blockIdx.y * NN;
    for (int i = tid; i < NN; i += THR)
        sp[i] = g_sorted[base + i];
    for (int i = tid; i <= NBKT; i += THR)
        scum[i] = g_cum[blockIdx.y * (NBKT + 1) + i];
    __syncthreads();

    int slab = blockIdx.x + 32 * slabq;
    int ws = slab * 32;
    int mid = ws + 16;
    int s = ws + lane;
    float4 pi = sp[s];

    int lo0 = mid - NEARW; if (lo0 < 0) lo0 = 0;
    int hi0 = mid + NEARW; if (hi0 > NN) hi0 = NN;

    float bd[KK];
    int bi[KK];
    const uint4* src = (const uint4*)&g_p1[((size_t)base + s) * KK];
#pragma unroll
    for (int t = 0; t < 8; t++) {
        uint4 v = src[t];
        bd[2 * t]     = __uint_as_float(v.x);  bi[2 * t]     = (int)v.y;
        bd[2 * t + 1] = __uint_as_float(v.z);  bi[2 * t + 1] = (int)v.w;
    }

    if (side == 0) {
        int cur = lo0;
        while (cur > 0) {
            float r = sqrtf(bd[KK - 1]) * 1.0001f;
            int lo = scum[qbucket(pi.x - r)];
            int Lw = (int)__reduce_min_sync(0xffffffffu, (unsigned)lo);
            if (Lw < 0) Lw = 0;
            if (Lw >= cur) break;
            int st = cur - CHK; if (st < Lw) st = Lw;
            scan_par(sp, buf, tid, st, cur, par, -1, pi, bd, bi);
            cur = st;
        }
    } else {
        int cur = hi0;
        while (cur < NN) {
            float r = sqrtf(bd[KK - 1]) * 1.0001f;
            int hi = scum[qbucket(pi.x + r) + 1];
            int Rw = (int)__reduce_max_sync(0xffffffffu, (unsigned)hi);
            if (Rw > NN) Rw = NN;
            if (Rw <= cur) break;
            int en = cur + CHK; if (en > Rw) en = Rw;
            scan_par(sp, buf, tid, cur, en, par, -1, pi, bd, bi);
            cur = en;
        }
    }

    if (q != 0) {
#pragma unroll
        for (int k = 0; k < KK; k++)
            lists[slabq * (3 * 32 * KK) + (q - 1) * (32 * KK) + k * 32 + lane] =
                make_uint2(__float_as_uint(bd[k]), (unsigned)bi[k]);
    }
    __syncthreads();

    if (q == 0) {
        // insert-merge siblings; skip near-range entries (shared P1 seeds)
#pragma unroll
        for (int l = 0; l < 3; l++) {
#pragma unroll
            for (int k = 0; k < KK; k++) {
                uint2 e = lists[slabq * (3 * 32 * KK) + l * (32 * KK) + k * 32 + lane];
                int j = (int)e.y;
                float d2 = __uint_as_float(e.x);
                if (d2 < bd[KK - 1] && (j < lo0 || j >= hi0))
                    insert16(bd, bi, d2, j);
            }
        }
        int iorig = __float_as_int(pi.w);
#pragma unroll
        for (int k = 0; k < KK; k++)
            g_nbr[(size_t)iorig * KK + k] = __float_as_int(sp[bi[k]].w);
    }
}

// ---------------- k3: edge kernel -------------------------------------------
__global__ void edge_kernel(const float* __restrict__ pos,
                            const float* __restrict__ W_pos,
                            const float* __restrict__ b_pos,
                            float* __restrict__ out) {
    int tid = threadIdx.x;
    int lane = tid & 31;
    int warp = tid >> 5;
    int i = blockIdx.x * 8 + warp;
    int c0 = lane * 2;

    float2 Wpa0 = *(const float2*)&g_Wpa[0 * 64 + c0];
    float2 Wpa1 = *(const float2*)&g_Wpa[1 * 64 + c0];
    float2 Wpa2 = *(const float2*)&g_Wpa[2 * 64 + c0];
    float2 Wp0  = *(const float2*)&W_pos[0 * 64 + c0];
    float2 Wp1  = *(const float2*)&W_pos[1 * 64 + c0];
    float2 Wp2  = *(const float2*)&W_pos[2 * 64 + c0];
    float2 bp   = *(const float2*)&b_pos[c0];
    float2 bL   = *(const float2*)&g_biasL[c0];
    float2 Ai   = *(const float2*)&g_A[(size_t)i * 64 + c0];
    float basex = Ai.x + bL.x;
    float basey = Ai.y + bL.y;

    float pix = pos[i * 3 + 0];
    float piy = pos[i * 3 + 1];
    float piz = pos[i * 3 + 2];

    int myn = (lane < KK) ? g_nbr[(size_t)i * KK + lane] : i;
    float mpx = pos[myn * 3 + 0];
    float mpy = pos[myn * 3 + 1];
    float mpz = pos[myn * 3 + 2];

    float sx = 0.f, sy = 0.f, ox = 0.f, oy = 0.f;

#pragma unroll 4
    for (int j = 0; j <= KK; j++) {
        int jj  = __shfl_sync(0xffffffffu, myn, j);
        float pjx = __shfl_sync(0xffffffffu, mpx, j);
        float pjy = __shfl_sync(0xffffffffu, mpy, j);
        float pjz = __shfl_sync(0xffffffffu, mpz, j);
        float dx = pix - pjx, dy = piy - pjy, dz = piz - pjz;

        float4 bv = *(const float4*)&g_BV[(size_t)jj * 128 + lane * 4];

        float lgx = basex - bv.x + dx * Wpa0.x + dy * Wpa1.x + dz * Wpa2.x;
        float lgy = basey - bv.y + dx * Wpa0.y + dy * Wpa1.y + dz * Wpa2.y;
        float px = __expf(lgx);
        float py = __expf(lgy);

        float dvx = dx * Wp0.x + dy * Wp1.x + dz * Wp2.x + bp.x;
        float dvy = dx * Wp0.y + dy * Wp1.y + dz * Wp2.y + bp.y;

        sx += px;
        sy += py;
        ox = fmaf(px, bv.z + dvx, ox);
        oy = fmaf(py, bv.w + dvy, oy);
    }

    float2 r;
    r.x = ox / sx;
    r.y = oy / sy;
    *(float2*)&out[(size_t)i * 64 + c0] = r;
}

// ---------------- launch: two-stream fork/join graph ------------------------
extern "C" void kernel_launch(void* const* d_in, const int* in_sizes, int n_in,
                              void* d_out, int out_size) {
    const float* x      = (const float*)d_in[0];
    const float* pos    = (const float*)d_in[1];
    const float* W_pos  = (const float*)d_in[3];
    const float* b_pos  = (const float*)d_in[4];
    const float* W_attn = (const float*)d_in[5];
    const float* b_attn = (const float*)d_in[6];
    const float* W_val  = (const float*)d_in[7];
    const float* W_src  = (const float*)d_in[8];
    const float* W_dst  = (const float*)d_in[9];
    float* out = (float*)d_out;

    static cudaStream_t s2 = nullptr;
    static cudaEvent_t evFork = nullptr, evJoin = nullptr;
    static bool smemSet = false;
    const int p1_smem = 32768 + 16384 + 24576;                   // 73728
    const int p2_smem = 32768 + 16384 + 24576 + (NBKT + 1 + 3) * 4;  // 74768
    if (!s2) {
        cudaStreamCreateWithFlags(&s2, cudaStreamNonBlocking);
        cudaEventCreateWithFlags(&evFork, cudaEventDisableTiming);
        cudaEventCreateWithFlags(&evJoin, cudaEventDisableTiming);
    }
    if (!smemSet) {
        cudaFuncSetAttribute(knn_p1_kernel,
                             cudaFuncAttributeMaxDynamicSharedMemorySize, p1_smem);
        cudaFuncSetAttribute(knn_p2_kernel,
                             cudaFuncAttributeMaxDynamicSharedMemorySize, p2_smem);
        smemSet = true;
    }

    cudaEventRecord(evFork, 0);
    cudaStreamWaitEvent(s2, evFork, 0);

    sort_kernel<<<BB, 1024, 0, s2>>>(pos);
    knn_p1_kernel<<<dim3(32, BB), THR, p1_smem, s2>>>();
    knn_p2_kernel<<<dim3(32, BB), THR, p2_smem, s2>>>();
    cudaEventRecord(evJoin, s2);

    combine_kernel<<<17, 256>>>(W_pos, b_pos, W_attn, b_attn, W_src, W_dst);
    feat_gemm_kernel<<<dim3(BN / 64, 3), 256>>>(x, W_val);

    cudaStreamWaitEvent(0, evJoin, 0);
    edge_kernel<<<BN / 8, 256>>>(pos, W_pos, b_pos, out);
}

// round 17
// speedup vs baseline: 1.2326x; 1.2326x over previous
#include <cuda_runtime.h>

#define BB 16
#define NN 2048
#define KK 16
#define CC 64
#define BN (BB * NN)

#define THR 256     // knn threads per block (8 warps = 4 slab pairs)
#define KBUF 24     // per-thread idx buffer entries
#define CHK 128     // steady-state chunk size

#define NBKT 256
#define QLO  (-6.0f)
#define QS   (256.0f / 12.0f)   // buckets per unit x

// ---------------- scratch ---------------------------------------------------
__device__ float  g_A  [BN * CC];
__device__ float  g_BV [BN * 2*CC];
__device__ int    g_nbr[BN * KK];
__device__ float4 g_sorted[BN];
__device__ int    g_cum[BB * (NBKT + 1)];
__device__ float  g_Wda[CC * CC];
__device__ float  g_Wsa[CC * CC];
__device__ float  g_Wpa[3 * CC];
__device__ float  g_biasL[CC];

__device__ __forceinline__ int qbucket(float x) {
    int b = (int)floorf((x - QLO) * QS);
    if (b < 0) b = 0;
    if (b > NBKT - 1) b = NBKT - 1;
    return b;
}

// ---------------- k0: combine weights ---------------------------------------
__global__ void combine_kernel(const float* __restrict__ W_pos,
                               const float* __restrict__ b_pos,
                               const float* __restrict__ W_attn,
                               const float* __restrict__ b_attn,
                               const float* __restrict__ W_src,
                               const float* __restrict__ W_dst) {
    int tid = threadIdx.x;
    int blk = blockIdx.x;
    if (blk < 16) {
        int r = tid >> 6, c = tid & 63;
        int k = blk * 4 + r;
        float a1 = 0.f, a2 = 0.f;
#pragma unroll 8
        for (int m = 0; m < 64; m++) {
            float w = W_attn[m * 64 + c];
            a1 = fmaf(W_dst[k * 64 + m], w, a1);
            a2 = fmaf(W_src[k * 64 + m], w, a2);
        }
        g_Wda[k * 64 + c] = a1;
        g_Wsa[k * 64 + c] = a2;
    } else {
        if (tid < 192) {
            int d = tid >> 6, c = tid & 63;
            float a = 0.f;
#pragma unroll 8
            for (int m = 0; m < 64; m++)
                a = fmaf(W_pos[d * 64 + m], W_attn[m * 64 + c], a);
            g_Wpa[tid] = a;
        } else {
            int c = tid - 192;
            float a = b_attn[c];
#pragma unroll 8
            for (int m = 0; m < 64; m++)
                a = fmaf(b_pos[m], W_attn[m * 64 + c], a);
            g_biasL[c] = a;
        }
    }
}

// ---------------- k1: per-point GEMMs ---------------------------------------
__global__ void feat_gemm_kernel(const float* __restrict__ x,
                                 const float* __restrict__ W_val) {
    __shared__ float xs[64][68];
    __shared__ float ws[64 * 64];
    int tid = threadIdx.x;
    int p0 = blockIdx.x * 64;
    int m = blockIdx.y;
    const float* src = (m == 0) ? g_Wda : (m == 1) ? g_Wsa : W_val;

    for (int idx = tid; idx < 4096; idx += 256) {
        int p = idx >> 6, k = idx & 63;
        xs[k][p] = x[(p0 + p) * 64 + k];
        ws[idx] = src[idx];
    }
    __syncthreads();

    int tx = tid & 15, ty = tid >> 4;
    float acc[4][4];
#pragma unroll
    for (int i = 0; i < 4; i++)
#pragma unroll
        for (int j = 0; j < 4; j++) acc[i][j] = 0.f;

#pragma unroll 8
    for (int k = 0; k < 64; k++) {
        float4 xv = *(const float4*)&xs[k][ty * 4];
        float4 wv = *(const float4*)&ws[k * 64 + tx * 4];
        acc[0][0] = fmaf(xv.x, wv.x, acc[0][0]);
        acc[0][1] = fmaf(xv.x, wv.y, acc[0][1]);
        acc[0][2] = fmaf(xv.x, wv.z, acc[0][2]);
        acc[0][3] = fmaf(xv.x, wv.w, acc[0][3]);
        acc[1][0] = fmaf(xv.y, wv.x, acc[1][0]);
        acc[1][1] = fmaf(xv.y, wv.y, acc[1][1]);
        acc[1][2] = fmaf(xv.y, wv.z, acc[1][2]);
        acc[1][3] = fmaf(xv.y, wv.w, acc[1][3]);
        acc[2][0] = fmaf(xv.z, wv.x, acc[2][0]);
        acc[2][1] = fmaf(xv.z, wv.y, acc[2][1]);
        acc[2][2] = fmaf(xv.z, wv.z, acc[2][2]);
        acc[2][3] = fmaf(xv.z, wv.w, acc[2][3]);
        acc[3][0] = fmaf(xv.w, wv.x, acc[3][0]);
        acc[3][1] = fmaf(xv.w, wv.y, acc[3][1]);
        acc[3][2] = fmaf(xv.w, wv.z, acc[3][2]);
        acc[3][3] = fmaf(xv.w, wv.w, acc[3][3]);
    }

    int c0 = tx * 4;
#pragma unroll
    for (int i = 0; i < 4; i++) {
        int p = p0 + ty * 4 + i;
        if (m == 0) {
            *(float4*)&g_A[(size_t)p * 64 + c0] =
                make_float4(acc[i][0], acc[i][1], acc[i][2], acc[i][3]);
        } else if (m == 1) {
            *(float2*)&g_BV[(size_t)p * 128 + c0 * 2]     = make_float2(acc[i][0], acc[i][1]);
            *(float2*)&g_BV[(size_t)p * 128 + c0 * 2 + 4] = make_float2(acc[i][2], acc[i][3]);
        } else {
            *(float2*)&g_BV[(size_t)p * 128 + c0 * 2 + 2] = make_float2(acc[i][0], acc[i][1]);
            *(float2*)&g_BV[(size_t)p * 128 + c0 * 2 + 6] = make_float2(acc[i][2], acc[i][3]);
        }
    }
}

// ---------------- k2a: per-cloud bucket (counting) sort by quantized x -------
__global__ void __launch_bounds__(1024) sort_kernel(const float* __restrict__ pos) {
    __shared__ int hist[NBKT];
    __shared__ int cum[NBKT + 1];
    __shared__ int cursor[NBKT];
    __shared__ int wsum[8];

    int tid = threadIdx.x;
    int lane = tid & 31;
    int w = tid >> 5;
    int base = blockIdx.x * NN;

    if (tid < NBKT) hist[tid] = 0;
    __syncthreads();

    float4 v[2];
    int b[2];
#pragma unroll
    for (int k = 0; k < 2; k++) {
        int i = tid + k * 1024;
        const float* p = pos + (size_t)(base + i) * 3;
        float px = p[0];
        v[k] = make_float4(px, p[1], p[2], __int_as_float(base + i));
        b[k] = qbucket(px);
        atomicAdd(&hist[b[k]], 1);
    }
    __syncthreads();

    if (tid < NBKT) {
        int val = hist[tid];
#pragma unroll
        for (int o = 1; o < 32; o <<= 1) {
            int n = __shfl_up_sync(0xffffffffu, val, o);
            if (lane >= o) val += n;
        }
        if (lane == 31) wsum[w] = val;
        __syncthreads();
        if (tid == 0) {
            int a = 0;
#pragma unroll
            for (int i = 0; i < 8; i++) { int t = wsum[i]; wsum[i] = a; a += t; }
        }
        __syncthreads();
        int incl = val + wsum[w];
        cum[tid + 1] = incl;
        if (tid == 0) cum[0] = 0;
    } else {
        __syncthreads();
        __syncthreads();
    }
    __syncthreads();

    if (tid < NBKT) cursor[tid] = cum[tid];
    if (tid <= NBKT) g_cum[blockIdx.x * (NBKT + 1) + tid] = cum[tid];
    __syncthreads();

#pragma unroll
    for (int k = 0; k < 2; k++) {
        int off = atomicAdd(&cursor[b[k]], 1);
        g_sorted[base + off] = v[k];
    }
}

// ---------------- knn helpers ------------------------------------------------
__device__ __forceinline__ void insert16(float (&bd)[KK], int (&bi)[KK],
                                         float d, int id) {
#pragma unroll
    for (int s = 0; s < KK; s++) {
        bool p = d < bd[s];
        float nbd = p ? d : bd[s];
        float nd  = p ? bd[s] : d;
        int   nbi = p ? id : bi[s];
        int   nid = p ? bi[s] : id;
        bd[s] = nbd; d = nd; bi[s] = nbi; id = nid;
    }
}

// full bitonic sort of 16 (ascending), parallel network (depth ~10 stages)
__device__ __forceinline__ void sort16(float (&d)[KK], int (&ix)[KK]) {
#pragma unroll
    for (int k = 2; k <= 16; k <<= 1)
#pragma unroll
        for (int j = k >> 1; j > 0; j >>= 1)
#pragma unroll
            for (int i = 0; i < 16; i++) {
                int l = i ^ j;
                if (l > i) {
                    bool up = ((i & k) == 0);
                    bool sw = up ? (d[i] > d[l]) : (d[i] < d[l]);
                    float tv = sw ? d[l] : d[i];
                    float tw = sw ? d[i] : d[l];
                    int   ui = sw ? ix[l] : ix[i];
                    int   uj = sw ? ix[i] : ix[l];
                    d[i] = tv; d[l] = tw; ix[i] = ui; ix[l] = uj;
                }
            }
}

// merge two ascending sorted 16-lists -> smallest 16 ascending (depth ~5)
__device__ __forceinline__ void merge16(float (&bd)[KK], int (&bi)[KK],
                                        const float (&ed)[KK], const int (&ei)[KK]) {
    float nd[KK];
    int ni[KK];
#pragma unroll
    for (int i = 0; i < KK; i++) {
        float od = ed[KK - 1 - i];
        int   oi = ei[KK - 1 - i];
        bool take = od < bd[i];
        nd[i] = take ? od : bd[i];
        ni[i] = take ? oi : bi[i];
    }
#pragma unroll
    for (int d = 8; d >= 1; d >>= 1)
#pragma unroll
        for (int i = 0; i < KK; i++) {
            int l = i | d;
            if (l != i) {
                bool sw = nd[i] > nd[l];
                float tv = sw ? nd[l] : nd[i];
                float tw = sw ? nd[i] : nd[l];
                int   ui = sw ? ni[l] : ni[i];
                int   uj = sw ? ni[i] : ni[l];
                nd[i] = tv; nd[l] = tw; ni[i] = ui; ni[l] = uj;
            }
        }
#pragma unroll
    for (int i = 0; i < KK; i++) { bd[i] = nd[i]; bi[i] = ni[i]; }
}

// broadcast scan [jb, je): buffered pushes, batched sort+merge drain at end.
// bd/bi stay sorted ascending throughout.
__device__ __forceinline__ void scan_range(const float4* __restrict__ sp,
                                           int* __restrict__ buf, int tid,
                                           int jb, int je, int s, float4 pi,
                                           float (&bd)[KK], int (&bi)[KK]) {
    int cnt = 0;
#pragma unroll 4
    for (int j = jb; j < je; j++) {
        float4 p = sp[j];
        float dx = pi.x - p.x, dy = pi.y - p.y, dz = pi.z - p.z;
        float d2 = fmaf(dx, dx, fmaf(dy, dy, dz * dz));
        if (d2 < bd[KK - 1] && j != s) {
            if (cnt < KBUF) { buf[cnt * THR + tid] = j; cnt++; }
            else insert16(bd, bi, d2, j);
        }
    }
    unsigned wmax = __reduce_max_sync(0xffffffffu, (unsigned)cnt);
    for (unsigned m0 = 0; m0 < wmax; m0 += KK) {
        float cd[KK];
        int ci[KK];
#pragma unroll
        for (int t = 0; t < KK; t++) {
            int mm = (int)m0 + t;
            if (mm < cnt) {
                int j = buf[mm * THR + tid];
                float4 p = sp[j];
                float dx = pi.x - p.x, dy = pi.y - p.y, dz = pi.z - p.z;
                cd[t] = fmaf(dx, dx, fmaf(dy, dy, dz * dz));
                ci[t] = j;
            } else {
                cd[t] = 3.4e38f;
                ci[t] = 0;
            }
        }
        sort16(cd, ci);
        merge16(bd, bi, cd, ci);
    }
}

// ---------------- k2b: pair-warp split windowed KNN --------------------------
__global__ void __launch_bounds__(THR) knn_kernel() {
    extern __shared__ char ksm[];
    float4* sp    = (float4*)ksm;                             // 32 KB
    int*    buf   = (int*)(ksm + 32768);                      // 24 KB
    uint2*  lists = (uint2*)(ksm + 32768 + 24576);            // 16 KB (transposed)
    int*    scum  = (int*)(ksm + 32768 + 24576 + 16384);      // 1040 B

    int tid  = threadIdx.x;
    int lane = tid & 31;
    int warp = tid >> 5;
    int pair = warp >> 1;     // 0..3
    int side = warp & 1;      // 0 = left (+merge), 1 = right

    int base = blockIdx.y * NN;
    for (int i = tid; i < NN; i += THR)
        sp[i] = g_sorted[base + i];
    for (int i = tid; i <= NBKT; i += THR)
        scum[i] = g_cum[blockIdx.y * (NBKT + 1) + i];
    __syncthreads();

    int slab = blockIdx.x + 16 * pair;  // 0..63, spread for balance
    int ws = slab * 32;
    int s = ws + lane;
    float4 pi = sp[s];
    int c0 = ws + 8, c1 = ws + 24;      // seed range (center of slab)

    float bd[KK];
    int bi[KK];
    // seed: center 16 ranks (broadcast); self -> +inf
#pragma unroll
    for (int t = 0; t < KK; t++) {
        int j = c0 + t;
        float4 p = sp[j];
        float dx = pi.x - p.x, dy = pi.y - p.y, dz = pi.z - p.z;
        float d2 = fmaf(dx, dx, fmaf(dy, dy, dz * dz));
        bd[t] = (j == s) ? 3.4e38f : d2;
        bi[t] = j;
    }
    sort16(bd, bi);

    if (side == 0) {
        // left side: geometric chunks downward 16, 32, 64 from c0
        int s1 = c0 - 16;  if (s1 < 0) s1 = 0;
        int s2 = c0 - 48;  if (s2 < 0) s2 = 0;
        int s3 = c0 - 112; if (s3 < 0) s3 = 0;
        scan_range(sp, buf, tid, s1, c0, s, pi, bd, bi);
        scan_range(sp, buf, tid, s2, s1, s, pi, bd, bi);
        scan_range(sp, buf, tid, s3, s2, s, pi, bd, bi);
        int cur = s3;
        while (cur > 0) {
            float r = sqrtf(bd[KK - 1]) * 1.0001f;
            int lo = scum[qbucket(pi.x - r)];
            int Lw = (int)__reduce_min_sync(0xffffffffu, (unsigned)lo);
            if (Lw < 0) Lw = 0;
            if (Lw >= cur) break;
            int st = cur - CHK; if (st < Lw) st = Lw;
            scan_range(sp, buf, tid, st, cur, s, pi, bd, bi);
            cur = st;
        }
    } else {
        // right side: geometric chunks upward 16, 32, 64 from c1
        int e1 = c1 + 16;  if (e1 > NN) e1 = NN;
        int e2 = c1 + 48;  if (e2 > NN) e2 = NN;
        int e3 = c1 + 112; if (e3 > NN) e3 = NN;
        scan_range(sp, buf, tid, c1, e1, s, pi, bd, bi);
        scan_range(sp, buf, tid, e1, e2, s, pi, bd, bi);
        scan_range(sp, buf, tid, e2, e3, s, pi, bd, bi);
        int cur = e3;
        while (cur < NN) {
            float r = sqrtf(bd[KK - 1]) * 1.0001f;
            int hi = scum[qbucket(pi.x + r) + 1];
            int Rw = (int)__reduce_max_sync(0xffffffffu, (unsigned)hi);
            if (Rw > NN) Rw = NN;
            if (Rw <= cur) break;
            int en = cur + CHK; if (en > Rw) en = Rw;
            scan_range(sp, buf, tid, cur, en, s, pi, bd, bi);
            cur = en;
        }
        // publish sorted right list, transposed (k*32 + lane)
#pragma unroll
        for (int k = 0; k < KK; k++)
            lists[pair * (KK * 32) + k * 32 + lane] =
                make_uint2(__float_as_uint(bd[k]), (unsigned)bi[k]);
    }

    __syncthreads();

    if (side == 0) {
        // load right list; kill seed-range duplicates; sort; bitonic pair-merge
        float ed[KK];
        int ei[KK];
#pragma unroll
        for (int k = 0; k < KK; k++) {
            uint2 e = lists[pair * (KK * 32) + k * 32 + lane];
            int j = (int)e.y;
            float d2 = __uint_as_float(e.x);
            bool dup = (j >= c0 && j < c1);
            ed[k] = dup ? 3.4e38f : d2;
            ei[k] = j;
        }
        sort16(ed, ei);
        merge16(bd, bi, ed, ei);

        int iorig = __float_as_int(pi.w);
#pragma unroll
        for (int k = 0; k < KK; k++)
            g_nbr[(size_t)iorig * KK + k] = __float_as_int(sp[bi[k]].w);
    }
}

// ---------------- k3: edge kernel -------------------------------------------
__global__ void edge_kernel(const float* __restrict__ pos,
                            const float* __restrict__ W_pos,
                            const float* __restrict__ b_pos,
                            float* __restrict__ out) {
    int tid = threadIdx.x;
    int lane = tid & 31;
    int warp = tid >> 5;
    int i = blockIdx.x * 8 + warp;
    int c0 = lane * 2;

    float2 Wpa0 = *(const float2*)&g_Wpa[0 * 64 + c0];
    float2 Wpa1 = *(const float2*)&g_Wpa[1 * 64 + c0];
    float2 Wpa2 = *(const float2*)&g_Wpa[2 * 64 + c0];
    float2 Wp0  = *(const float2*)&W_pos[0 * 64 + c0];
    float2 Wp1  = *(const float2*)&W_pos[1 * 64 + c0];
    float2 Wp2  = *(const float2*)&W_pos[2 * 64 + c0];
    float2 bp   = *(const float2*)&b_pos[c0];
    float2 bL   = *(const float2*)&g_biasL[c0];
    float2 Ai   = *(const float2*)&g_A[(size_t)i * 64 + c0];
    float basex = Ai.x + bL.x;
    float basey = Ai.y + bL.y;

    float pix = pos[i * 3 + 0];
    float piy = pos[i * 3 + 1];
    float piz = pos[i * 3 + 2];

    int myn = (lane < KK) ? g_nbr[(size_t)i * KK + lane] : i;
    float mpx = pos[myn * 3 + 0];
    float mpy = pos[myn * 3 + 1];
    float mpz = pos[myn * 3 + 2];

    float sx = 0.f, sy = 0.f, ox = 0.f, oy = 0.f;

#pragma unroll 4
    for (int j = 0; j <= KK; j++) {
        int jj  = __shfl_sync(0xffffffffu, myn, j);
        float pjx = __shfl_sync(0xffffffffu, mpx, j);
        float pjy = __shfl_sync(0xffffffffu, mpy, j);
        float pjz = __shfl_sync(0xffffffffu, mpz, j);
        float dx = pix - pjx, dy = piy - pjy, dz = piz - pjz;

        float4 bv = *(const float4*)&g_BV[(size_t)jj * 128 + lane * 4];

        float lgx = basex - bv.x + dx * Wpa0.x + dy * Wpa1.x + dz * Wpa2.x;
        float lgy = basey - bv.y + dx * Wpa0.y + dy * Wpa1.y + dz * Wpa2.y;
        float px = __expf(lgx);
        float py = __expf(lgy);

        float dvx = dx * Wp0.x + dy * Wp1.x + dz * Wp2.x + bp.x;
        float dvy = dx * Wp0.y + dy * Wp1.y + dz * Wp2.y + bp.y;

        sx += px;
        sy += py;
        ox = fmaf(px, bv.z + dvx, ox);
        oy = fmaf(py, bv.w + dvy, oy);
    }

    float2 r;
    r.x = ox / sx;
    r.y = oy / sy;
    *(float2*)&out[(size_t)i * 64 + c0] = r;
}

// ---------------- launch: two-stream fork/join graph ------------------------
extern "C" void kernel_launch(void* const* d_in, const int* in_sizes, int n_in,
                              void* d_out, int out_size) {
    const float* x      = (const float*)d_in[0];
    const float* pos    = (const float*)d_in[1];
    const float* W_pos  = (const float*)d_in[3];
    const float* b_pos  = (const float*)d_in[4];
    const float* W_attn = (const float*)d_in[5];
    const float* b_attn = (const float*)d_in[6];
    const float* W_val  = (const float*)d_in[7];
    const float* W_src  = (const float*)d_in[8];
    const float* W_dst  = (const float*)d_in[9];
    float* out = (float*)d_out;

    static cudaStream_t s2 = nullptr;
    static cudaEvent_t evFork = nullptr, evJoin = nullptr;
    static bool smemSet = false;
    const int knn_smem = 32768 + KBUF * THR * 4 + 4 * 32 * KK * 8
                       + (NBKT + 1 + 3) * 4;   // 32K + 24K + 16K + 1040
    if (!s2) {
        cudaStreamCreateWithFlags(&s2, cudaStreamNonBlocking);
        cudaEventCreateWithFlags(&evFork, cudaEventDisableTiming);
        cudaEventCreateWithFlags(&evJoin, cudaEventDisableTiming);
    }
    if (!smemSet) {
        cudaFuncSetAttribute(knn_kernel,
                             cudaFuncAttributeMaxDynamicSharedMemorySize,
                             knn_smem);
        smemSet = true;
    }

    // fork: chain B (sort -> knn) on s2, chain A (combine -> feat) on default
    cudaEventRecord(evFork, 0);
    cudaStreamWaitEvent(s2, evFork, 0);

    sort_kernel<<<BB, 1024, 0, s2>>>(pos);
    knn_kernel<<<dim3(16, BB), THR, knn_smem, s2>>>();
    cudaEventRecord(evJoin, s2);

    combine_kernel<<<17, 256>>>(W_pos, b_pos, W_attn, b_attn, W_src, W_dst);
    feat_gemm_kernel<<<dim3(BN / 64, 3), 256>>>(x, W_val);

    // join: edge needs both chains
    cudaStreamWaitEvent(0, evJoin, 0);
    edge_kernel<<<BN / 8, 256>>>(pos, W_pos, b_pos, out);
}